// round 2
// baseline (speedup 1.0000x reference)
#include <cuda_runtime.h>
#include <cuda_bf16.h>

// InfoNCE loss:
//   inputs (metadata order): embeddings f32 [100000,128], targets i32 [16384],
//                            contexts i32 [16384], negatives i32 [16384,20]
//   (reference is int64, but the harness maps integer tensors to int32 buffers)
//   output: scalar f32 loss
//
// One warp per batch element. Lane l holds float4 of target row (coalesced
// 512B warp gather). 21 gathered rows -> 21 dots via per-lane FMA + butterfly
// shuffle reduction. Full unroll -> ~21 LDG.128 in flight per lane to hide L2
// latency (table fits in 126MB L2 -> L2-BW bound).

#define BATCH   16384
#define DIM     128
#define NUM_NEG 20
#define NLOGITS (NUM_NEG + 1)
#define INV_T   (1.0f / 0.07f)

__global__ void zero_kernel(float* out) {
    out[0] = 0.0f;
}

__global__ __launch_bounds__(256) void infonce_kernel(
    const float* __restrict__ emb,
    const int* __restrict__ targets,
    const int* __restrict__ contexts,
    const int* __restrict__ negatives,
    float* __restrict__ out)
{
    const int lane = threadIdx.x & 31;
    const int warp_in_blk = threadIdx.x >> 5;
    const int b = (blockIdx.x * (blockDim.x >> 5)) + warp_in_blk;

    float loss = 0.0f;
    if (b < BATCH) {
        const float4* __restrict__ e4 = (const float4*)emb;

        // target row: lane l -> elements [4l, 4l+4)
        const int ti = targets[b];
        const float4 t = e4[(size_t)ti * 32 + lane];

        // gather indices: context first, then 20 negatives
        int idx[NLOGITS];
        idx[0] = contexts[b];
        #pragma unroll
        for (int k = 0; k < NUM_NEG; k++)
            idx[k + 1] = negatives[b * NUM_NEG + k];

        // 21 partial dots — fully unrolled so loads batch up (high MLP)
        float s[NLOGITS];
        #pragma unroll
        for (int k = 0; k < NLOGITS; k++) {
            const float4 v = e4[(size_t)idx[k] * 32 + lane];
            s[k] = fmaf(t.x, v.x, fmaf(t.y, v.y, fmaf(t.z, v.z, t.w * v.w)));
        }

        // butterfly reduce each logit across the warp
        #pragma unroll
        for (int k = 0; k < NLOGITS; k++) {
            float x = s[k];
            x += __shfl_xor_sync(0xFFFFFFFFu, x, 16);
            x += __shfl_xor_sync(0xFFFFFFFFu, x, 8);
            x += __shfl_xor_sync(0xFFFFFFFFu, x, 4);
            x += __shfl_xor_sync(0xFFFFFFFFu, x, 2);
            x += __shfl_xor_sync(0xFFFFFFFFu, x, 1);
            s[k] = x * INV_T;
        }

        // every lane now has all 21 logits; compute -log_softmax[0]
        float m = s[0];
        #pragma unroll
        for (int k = 1; k < NLOGITS; k++) m = fmaxf(m, s[k]);
        float sum = 0.0f;
        #pragma unroll
        for (int k = 0; k < NLOGITS; k++) sum += __expf(s[k] - m);
        loss = (m + __logf(sum) - s[0]) * (1.0f / (float)BATCH);
    }

    // block reduce: 8 warps -> smem -> one atomicAdd per block
    __shared__ float part[8];
    if (lane == 0) part[warp_in_blk] = loss;
    __syncthreads();
    if (threadIdx.x == 0) {
        float tot = 0.0f;
        #pragma unroll
        for (int w = 0; w < 8; w++) tot += part[w];
        atomicAdd(out, tot);
    }
}

extern "C" void kernel_launch(void* const* d_in, const int* in_sizes, int n_in,
                              void* d_out, int out_size) {
    const float* emb = (const float*)d_in[0];
    const int*   tgt = (const int*)d_in[1];
    const int*   ctx = (const int*)d_in[2];
    const int*   neg = (const int*)d_in[3];
    float* out = (float*)d_out;

    zero_kernel<<<1, 1>>>(out);

    const int warps_per_block = 8;  // 256 threads
    const int blocks = (BATCH + warps_per_block - 1) / warps_per_block;  // 2048
    infonce_kernel<<<blocks, warps_per_block * 32>>>(emb, tgt, ctx, neg, out);
}